// round 9
// baseline (speedup 1.0000x reference)
#include <cuda_runtime.h>
#include <math_constants.h>
#include <cstdint>

namespace {
constexpr int B  = 4;
constexpr int S  = 2048;
constexpr int H  = 1024;
constexpr int NH = 16;
constexpr int HD = 64;
constexpr int MROWS = B * S;  // 8192
constexpr size_t OUT_ELEMS  = (size_t)B * S * H;
constexpr size_t ATTN_ELEMS = (size_t)B * NH * S * S;

constexpr int ASTR = 132;   // tf32 staging stride (floats)
constexpr int KSTR = 68;    // raw K tile stride (floats)  (68%32==4 -> cf)
constexpr int VSTR = 72;    // raw V tile stride (floats)  (72%32==8 -> cf)

// flash smem layout (bytes)
constexpr size_t FQ  = 0;                        // u32 [64][ASTR] Q tf32 [k][m]
constexpr size_t FK  = FQ  + 64  * ASTR * 4;     // f32 raw K [j=128][KSTR]
constexpr size_t FV  = FK  + 128 * KSTR * 4;     // f32 raw V x2 [128][VSTR]
constexpr size_t FP  = FV  + 2 * 128 * VSTR * 4; // u32 [m=128][ASTR] tf32 exp(P)
constexpr size_t FM  = FP  + 128 * ASTR * 4;
constexpr size_t FL  = FM  + 128 * 4;
constexpr size_t FMN = FL  + 128 * 4;
constexpr size_t FF  = FMN + 128 * 4;
constexpr size_t FR2 = FF  + 128 * 4;
constexpr size_t FTOT = FR2 + 128 * 4 * 4;       // ~209 KB
}

__device__ float g_q[(size_t)B * NH * S * HD];
__device__ float g_k[(size_t)B * NH * S * HD];
__device__ float g_v[(size_t)B * NH * S * HD];
__device__ float g_ctx[(size_t)B * S * H];
__device__ float g_m[(size_t)B * NH * S];
__device__ float g_linv[(size_t)B * NH * S];
__device__ float g_attn_fb[ATTN_ELEMS];

__device__ __forceinline__ uint32_t tf32_of(float x) {
    uint32_t y;
    asm("cvt.rna.tf32.f32 %0, %1;" : "=r"(y) : "f"(x));
    return y;
}
__device__ __forceinline__ void mma8(float c[4],
                                     uint32_t a0, uint32_t a1, uint32_t a2, uint32_t a3,
                                     uint32_t b0, uint32_t b1) {
    asm volatile(
        "mma.sync.aligned.m16n8k8.row.col.f32.tf32.tf32.f32 "
        "{%0,%1,%2,%3}, {%4,%5,%6,%7}, {%8,%9}, {%0,%1,%2,%3};"
        : "+f"(c[0]), "+f"(c[1]), "+f"(c[2]), "+f"(c[3])
        : "r"(a0), "r"(a1), "r"(a2), "r"(a3), "r"(b0), "r"(b1));
}
__device__ __forceinline__ void cp16(uint32_t s, const void* g) {
    asm volatile("cp.async.cg.shared.global [%0], [%1], 16;" :: "r"(s), "l"(g));
}
#define CP_COMMIT()  asm volatile("cp.async.commit_group;")
#define CP_WAIT(N)   asm volatile("cp.async.wait_group %0;" :: "n"(N))

// ---------------------------------------------------------------------------
// GEMM: C[M,N] = A[M,K] @ W[N,K]^T + bias[N]. cp.async double-buffered.
// Raw f32 smem [row][k] stride 20; tf32 cvt at fragment load.
// ---------------------------------------------------------------------------
template <int MODE>
__global__ __launch_bounds__(256, 2) void gemm_tf32(
    const float* __restrict__ A, const float* __restrict__ W,
    const float* __restrict__ bias, float* __restrict__ C,
    int M, int N, int K)
{
    __shared__ __align__(16) float As[2][128][20];
    __shared__ __align__(16) float Ws[2][128][20];

    const int tid  = threadIdx.x;
    const int lane = tid & 31, wid = tid >> 5;
    const int row0 = blockIdx.y * 128, col0 = blockIdx.x * 128;
    const int wm = (wid >> 2) * 64, wn = (wid & 3) * 32;
    const int g = lane >> 2, tig = lane & 3;

    // loader: thread covers row (tid>>1), 2 x 16B segs
    const int lrow = tid >> 1;
    const int lseg = (tid & 1) * 8;   // float offset: 0 or 8

    auto issue = [&](int buf, int k0) {
        const float* ga = A + (size_t)(row0 + lrow) * K + k0 + lseg;
        uint32_t sa = (uint32_t)__cvta_generic_to_shared(&As[buf][lrow][lseg]);
        cp16(sa, ga); cp16(sa + 16, ga + 4);
        const float* gw = W + (size_t)(col0 + lrow) * K + k0 + lseg;
        uint32_t sw = (uint32_t)__cvta_generic_to_shared(&Ws[buf][lrow][lseg]);
        cp16(sw, gw); cp16(sw + 16, gw + 4);
        CP_COMMIT();
    };

    float acc[4][4][4] = {};
    issue(0, 0);

    int cur = 0;
    for (int k0 = 0; k0 < K; k0 += 16) {
        if (k0 + 16 < K) { issue(cur ^ 1, k0 + 16); CP_WAIT(1); }
        else             { CP_WAIT(0); }
        __syncthreads();

#pragma unroll
        for (int kk = 0; kk < 16; kk += 8) {
            uint32_t a[4][4], b[4][2];
#pragma unroll
            for (int mt = 0; mt < 4; mt++) {
                int m = wm + mt * 16 + g;
                a[mt][0] = tf32_of(As[cur][m][kk + tig]);
                a[mt][1] = tf32_of(As[cur][m + 8][kk + tig]);
                a[mt][2] = tf32_of(As[cur][m][kk + tig + 4]);
                a[mt][3] = tf32_of(As[cur][m + 8][kk + tig + 4]);
            }
#pragma unroll
            for (int nt = 0; nt < 4; nt++) {
                int n = wn + nt * 8 + g;
                b[nt][0] = tf32_of(Ws[cur][n][kk + tig]);
                b[nt][1] = tf32_of(Ws[cur][n][kk + tig + 4]);
            }
#pragma unroll
            for (int mt = 0; mt < 4; mt++)
#pragma unroll
                for (int nt = 0; nt < 4; nt++)
                    mma8(acc[mt][nt], a[mt][0], a[mt][1], a[mt][2], a[mt][3],
                         b[nt][0], b[nt][1]);
        }
        __syncthreads();
        cur ^= 1;
    }

#pragma unroll
    for (int mt = 0; mt < 4; mt++) {
#pragma unroll
        for (int rr = 0; rr < 2; rr++) {
            int m = row0 + wm + mt * 16 + g + rr * 8;
#pragma unroll
            for (int nt = 0; nt < 4; nt++) {
                int n = col0 + wn + nt * 8 + 2 * tig;
                float v0 = acc[mt][nt][rr * 2 + 0] + bias[n];
                float v1 = acc[mt][nt][rr * 2 + 1] + bias[n + 1];
                if (MODE == 0) {
                    *reinterpret_cast<float2*>(C + (size_t)m * N + n) =
                        make_float2(v0, v1);
                } else {
                    int bb = m / S, ss = m % S;
                    int hh2 = n / HD, dd = n % HD;
                    *reinterpret_cast<float2*>(
                        C + (((size_t)bb * NH + hh2) * S + ss) * HD + dd) =
                        make_float2(v0, v1);
                }
            }
        }
    }
}

// ---------------------------------------------------------------------------
// Flash attention, cp.async-pipelined. V double-buffered (issued 1 tile
// ahead), K single-buffered (issued mid-iteration after score mma).
// ---------------------------------------------------------------------------
__global__ __launch_bounds__(256) void flash_attn(
    const float* __restrict__ Qp, const float* __restrict__ Kp,
    const float* __restrict__ Vp, float* __restrict__ attn,
    float* __restrict__ ctx, float* __restrict__ mout,
    float* __restrict__ linvout, const int* __restrict__ causal_p)
{
    extern __shared__ char smc[];
    uint32_t* Qs   = reinterpret_cast<uint32_t*>(smc + FQ);
    float*    Kraw = reinterpret_cast<float*>(smc + FK);
    float*    Vraw = reinterpret_cast<float*>(smc + FV);
    uint32_t* Ps   = reinterpret_cast<uint32_t*>(smc + FP);
    float* m_s  = reinterpret_cast<float*>(smc + FM);
    float* l_s  = reinterpret_cast<float*>(smc + FL);
    float* mn_s = reinterpret_cast<float*>(smc + FMN);
    float* f_s  = reinterpret_cast<float*>(smc + FF);
    float* r2   = reinterpret_cast<float*>(smc + FR2);

    const int row0 = ((int)gridDim.x - 1 - (int)blockIdx.x) * 128;
    const int z    = blockIdx.y;
    const int causal = *causal_p;

    const float* Qg = Qp + (size_t)z * S * HD;
    const float* Kg = Kp + (size_t)z * S * HD;
    const float* Vg = Vp + (size_t)z * S * HD;
    float* att = attn + (size_t)z * S * S;

    const int tid = threadIdx.x;
    const int lane = tid & 31, wid = tid >> 5;
    const int g = lane >> 2, tig = lane & 3;
    const int lr = tid >> 2, lk = (tid & 3) << 2;
    const float NEG = -CUDART_INF_F;

    const int wm  = (wid >> 2) * 64, wn  = (wid & 3) * 32;   // score warps 2x4
    const int wm2 = (wid >> 1) * 32, wn2 = (wid & 1) * 32;   // PV warps 4x2

    // loader indices (K/V tiles: 128 rows x 64 floats)
    const int trow = tid >> 1;
    const int tseg = (tid & 1) * 32;  // float offset 0 / 32 (8 x 16B chunks)

    auto issueK = [&](int j0) {
        const float* gk = Kg + (size_t)(j0 + trow) * HD + tseg;
        uint32_t sk = (uint32_t)__cvta_generic_to_shared(&Kraw[trow * KSTR + tseg]);
#pragma unroll
        for (int c = 0; c < 8; c++) cp16(sk + c * 16, gk + c * 4);
    };
    auto issueV = [&](int vb, int j0) {
        const float* gv = Vg + (size_t)(j0 + trow) * HD + tseg;
        uint32_t sv = (uint32_t)__cvta_generic_to_shared(
            &Vraw[(size_t)vb * 128 * VSTR + trow * VSTR + tseg]);
#pragma unroll
        for (int c = 0; c < 8; c++) cp16(sv + c * 16, gv + c * 4);
    };

    const int jend   = causal ? (row0 + 128) : S;
    const int ntiles = jend >> 7;

    // prologue: V(0) + K(0) as one group
    issueV(0, 0);
    issueK(0);
    CP_COMMIT();

    // load Q (128 x 64) -> tf32 [k][m]
#pragma unroll
    for (int k0 = 0; k0 < HD; k0 += 16) {
#pragma unroll
        for (int hh = 0; hh < 2; hh++) {
            int r = lr + hh * 64;
            float4 v = *reinterpret_cast<const float4*>(
                Qg + (size_t)(row0 + r) * HD + k0 + lk);
            Qs[(k0 + lk + 0) * ASTR + r] = tf32_of(v.x);
            Qs[(k0 + lk + 1) * ASTR + r] = tf32_of(v.y);
            Qs[(k0 + lk + 2) * ASTR + r] = tf32_of(v.z);
            Qs[(k0 + lk + 3) * ASTR + r] = tf32_of(v.w);
        }
    }
    if (tid < 128) { m_s[tid] = NEG; l_s[tid] = 0.f; }

    float acc2[2][4][4] = {};

    for (int ti = 0; ti < ntiles; ti++) {
        const int j0 = ti << 7;
        const int vb = ti & 1;
        const bool more = (ti + 1) < ntiles;

        if (more) { issueV(vb ^ 1, j0 + 128); CP_COMMIT(); CP_WAIT(1); }
        else      { CP_WAIT(0); }
        __syncthreads();   // K(ti), V(ti) visible; Q/stats ready on ti==0

        // --- scores: Q (tf32 smem) x K (raw smem, cvt on load) ---
        float acc[4][4][4] = {};
#pragma unroll
        for (int kk = 0; kk < HD; kk += 8) {
            uint32_t a[4][4], b[4][2];
#pragma unroll
            for (int mt = 0; mt < 4; mt++) {
                int m = wm + mt * 16 + g;
                a[mt][0] = Qs[(kk + tig) * ASTR + m];
                a[mt][1] = Qs[(kk + tig) * ASTR + m + 8];
                a[mt][2] = Qs[(kk + tig + 4) * ASTR + m];
                a[mt][3] = Qs[(kk + tig + 4) * ASTR + m + 8];
            }
#pragma unroll
            for (int nt = 0; nt < 4; nt++) {
                int n = wn + nt * 8 + g;
                b[nt][0] = tf32_of(Kraw[n * KSTR + kk + tig]);
                b[nt][1] = tf32_of(Kraw[n * KSTR + kk + tig + 4]);
            }
#pragma unroll
            for (int mt = 0; mt < 4; mt++)
#pragma unroll
                for (int nt = 0; nt < 4; nt++)
                    mma8(acc[mt][nt], a[mt][0], a[mt][1], a[mt][2], a[mt][3],
                         b[nt][0], b[nt][1]);
        }

        // --- scale + mask + raw attn write + row-max partials ---
#pragma unroll
        for (int mt = 0; mt < 4; mt++) {
#pragma unroll
            for (int rr = 0; rr < 2; rr++) {
                int lm = wm + mt * 16 + g + rr * 8;
                int m  = row0 + lm;
                float mx = NEG;
#pragma unroll
                for (int nt = 0; nt < 4; nt++) {
                    int n = j0 + wn + nt * 8 + 2 * tig;
                    float v0 = acc[mt][nt][rr * 2 + 0] * 0.125f;
                    float v1 = acc[mt][nt][rr * 2 + 1] * 0.125f;
                    if (causal) {
                        if (n > m)     v0 = NEG;
                        if (n + 1 > m) v1 = NEG;
                    }
                    acc[mt][nt][rr * 2 + 0] = v0;
                    acc[mt][nt][rr * 2 + 1] = v1;
                    mx = fmaxf(mx, fmaxf(v0, v1));
                    *reinterpret_cast<float2*>(att + (size_t)m * S + n) =
                        make_float2(v0, v1);
                }
                mx = fmaxf(mx, __shfl_xor_sync(0xffffffffu, mx, 1));
                mx = fmaxf(mx, __shfl_xor_sync(0xffffffffu, mx, 2));
                if (tig == 0) r2[lm * 4 + (wid & 3)] = mx;
            }
        }
        __syncthreads();   // B: score mma done, K consumed

        // prefetch next K while exp/PV run
        if (more) { issueK(j0 + 128); CP_COMMIT(); }

        if (tid < 128) {
            float mn = fmaxf(fmaxf(r2[tid * 4 + 0], r2[tid * 4 + 1]),
                             fmaxf(r2[tid * 4 + 2], r2[tid * 4 + 3]));
            mn = fmaxf(m_s[tid], mn);
            mn_s[tid] = mn;
            f_s[tid]  = __expf(m_s[tid] - mn);
        }
        __syncthreads();   // C

        // --- exp, stage tf32 P, row-sum partials ---
#pragma unroll
        for (int mt = 0; mt < 4; mt++) {
#pragma unroll
            for (int rr = 0; rr < 2; rr++) {
                int lm = wm + mt * 16 + g + rr * 8;
                float mn = mn_s[lm];
                float sme = 0.f;
#pragma unroll
                for (int nt = 0; nt < 4; nt++) {
                    int nl = wn + nt * 8 + 2 * tig;
                    float e0 = __expf(acc[mt][nt][rr * 2 + 0] - mn);
                    float e1 = __expf(acc[mt][nt][rr * 2 + 1] - mn);
                    sme += e0 + e1;
                    uint2 pe = make_uint2(tf32_of(e0), tf32_of(e1));
                    *reinterpret_cast<uint2*>(&Ps[lm * ASTR + nl]) = pe;
                }
                sme += __shfl_xor_sync(0xffffffffu, sme, 1);
                sme += __shfl_xor_sync(0xffffffffu, sme, 2);
                if (tig == 0) r2[lm * 4 + (wid & 3)] = sme;
            }
        }
        __syncthreads();   // D

        if (tid < 128) {
            float add = r2[tid * 4 + 0] + r2[tid * 4 + 1] +
                        r2[tid * 4 + 2] + r2[tid * 4 + 3];
            l_s[tid] = l_s[tid] * f_s[tid] + add;
            m_s[tid] = mn_s[tid];
        }

        // --- PV: rescale acc2, then P (tf32 smem) x V (raw smem, cvt) ---
#pragma unroll
        for (int mt = 0; mt < 2; mt++) {
#pragma unroll
            for (int rr = 0; rr < 2; rr++) {
                float f = f_s[wm2 + mt * 16 + g + rr * 8];
#pragma unroll
                for (int nt = 0; nt < 4; nt++) {
                    acc2[mt][nt][rr * 2 + 0] *= f;
                    acc2[mt][nt][rr * 2 + 1] *= f;
                }
            }
        }
        const float* Vb = Vraw + (size_t)vb * 128 * VSTR;
#pragma unroll
        for (int kk = 0; kk < 128; kk += 8) {
            uint32_t a[2][4], b[4][2];
#pragma unroll
            for (int mt = 0; mt < 2; mt++) {
                int m = wm2 + mt * 16 + g;
                a[mt][0] = Ps[m * ASTR + kk + tig];
                a[mt][1] = Ps[(m + 8) * ASTR + kk + tig];
                a[mt][2] = Ps[m * ASTR + kk + tig + 4];
                a[mt][3] = Ps[(m + 8) * ASTR + kk + tig + 4];
            }
#pragma unroll
            for (int nt = 0; nt < 4; nt++) {
                int n = wn2 + nt * 8 + g;
                b[nt][0] = tf32_of(Vb[(kk + tig) * VSTR + n]);
                b[nt][1] = tf32_of(Vb[(kk + tig + 4) * VSTR + n]);
            }
#pragma unroll
            for (int mt = 0; mt < 2; mt++)
#pragma unroll
                for (int nt = 0; nt < 4; nt++)
                    mma8(acc2[mt][nt], a[mt][0], a[mt][1], a[mt][2], a[mt][3],
                         b[nt][0], b[nt][1]);
        }
        __syncthreads();   // E: Ps/V consumed; stats updated
    }

    if (tid < 128) {
        float inv = 1.0f / l_s[tid];
        f_s[tid] = inv;
        mout[(size_t)z * S + row0 + tid]    = m_s[tid];
        linvout[(size_t)z * S + row0 + tid] = inv;
    }
    __syncthreads();

    const int bb = z / NH, hh2 = z % NH;
#pragma unroll
    for (int mt = 0; mt < 2; mt++) {
#pragma unroll
        for (int rr = 0; rr < 2; rr++) {
            int lm = wm2 + mt * 16 + g + rr * 8;
            float inv = f_s[lm];
            int m = row0 + lm;
#pragma unroll
            for (int nt = 0; nt < 4; nt++) {
                int n = wn2 + nt * 8 + 2 * tig;
                *reinterpret_cast<float2*>(
                    ctx + ((size_t)bb * S + m) * H + hh2 * HD + n) =
                    make_float2(acc2[mt][nt][rr * 2 + 0] * inv,
                                acc2[mt][nt][rr * 2 + 1] * inv);
            }
        }
    }
}

// ---------------------------------------------------------------------------
// Normalize attn: p = exp(raw - m) * linv for cols <= r; 0 above.
// ---------------------------------------------------------------------------
__global__ __launch_bounds__(256) void normalize_attn(
    float* __restrict__ attn, const float* __restrict__ mrow,
    const float* __restrict__ linv, const int* __restrict__ causal_p)
{
    const size_t row = blockIdx.x;
    const int causal = *causal_p;
    const int r = causal ? (int)(row % S) : (S - 1);
    const float m  = mrow[row];
    const float il = linv[row];
    float* p = attn + row * S;
    const int t = threadIdx.x;

#pragma unroll
    for (int it = 0; it < 2; it++) {
        int c = (t + 256 * it) << 2;
        float4 v = make_float4(0.f, 0.f, 0.f, 0.f);
        if (c <= r) {
            float4 raw = *reinterpret_cast<const float4*>(p + c);
            v.x = __expf(raw.x - m) * il;
            v.y = (c + 1 <= r) ? __expf(raw.y - m) * il : 0.f;
            v.z = (c + 2 <= r) ? __expf(raw.z - m) * il : 0.f;
            v.w = (c + 3 <= r) ? __expf(raw.w - m) * il : 0.f;
        }
        *reinterpret_cast<float4*>(p + c) = v;
    }
}

// ---------------------------------------------------------------------------
// Launch
// ---------------------------------------------------------------------------
extern "C" void kernel_launch(void* const* d_in, const int* in_sizes, int n_in,
                              void* d_out, int out_size)
{
    const float* query = (const float*)d_in[0];
    const float* key_  = (const float*)d_in[1];
    const float* value = (const float*)d_in[2];
    const float* Wq = (const float*)d_in[3];
    const float* bq = (const float*)d_in[4];
    const float* Wk = (const float*)d_in[5];
    const float* bk = (const float*)d_in[6];
    const float* Wv = (const float*)d_in[7];
    const float* bv = (const float*)d_in[8];
    const float* Wo = (const float*)d_in[9];
    const float* bo = (const float*)d_in[10];
    const int* causal = (const int*)d_in[11];

    float *qp, *kp, *vp, *cp, *mp, *lp, *afb;
    cudaGetSymbolAddress((void**)&qp, g_q);
    cudaGetSymbolAddress((void**)&kp, g_k);
    cudaGetSymbolAddress((void**)&vp, g_v);
    cudaGetSymbolAddress((void**)&cp, g_ctx);
    cudaGetSymbolAddress((void**)&mp, g_m);
    cudaGetSymbolAddress((void**)&lp, g_linv);
    cudaGetSymbolAddress((void**)&afb, g_attn_fb);

    float* out = (float*)d_out;
    float* attn = ((size_t)out_size >= OUT_ELEMS + ATTN_ELEMS) ? (out + OUT_ELEMS)
                                                               : afb;

    cudaFuncSetAttribute(flash_attn,
                         cudaFuncAttributeMaxDynamicSharedMemorySize,
                         (int)FTOT);

    dim3 gproj(H / 128, MROWS / 128);                 // (8, 64)
    gemm_tf32<1><<<gproj, 256>>>(query, Wq, bq, qp, MROWS, H, H);
    gemm_tf32<1><<<gproj, 256>>>(key_,  Wk, bk, kp, MROWS, H, H);
    gemm_tf32<1><<<gproj, 256>>>(value, Wv, bv, vp, MROWS, H, H);

    dim3 gfa(S / 128, B * NH);                        // (16, 64)
    flash_attn<<<gfa, 256, FTOT>>>(qp, kp, vp, attn, cp, mp, lp, causal);

    normalize_attn<<<B * NH * S, 256>>>(attn, mp, lp, causal);

    gemm_tf32<0><<<gproj, 256>>>(cp, Wo, bo, out, MROWS, H, H);
}

// round 10
// speedup vs baseline: 1.0026x; 1.0026x over previous
#include <cuda_runtime.h>
#include <math_constants.h>
#include <cstdint>

namespace {
constexpr int B  = 4;
constexpr int S  = 2048;
constexpr int H  = 1024;
constexpr int NH = 16;
constexpr int HD = 64;
constexpr int MROWS = B * S;  // 8192
constexpr size_t OUT_ELEMS  = (size_t)B * S * H;
constexpr size_t ATTN_ELEMS = (size_t)B * NH * S * S;

constexpr int ASTR = 132;   // tf32 staging stride (floats)
constexpr int KSTR = 68;    // raw K tile stride (floats)  (68%32==4 -> cf)
constexpr int VSTR = 72;    // raw V tile stride (floats)  (72%32==8 -> cf)

// flash smem layout (bytes)
constexpr size_t FQ  = 0;                        // u32 [64][ASTR] Q tf32 [k][m]
constexpr size_t FK  = FQ  + 64  * ASTR * 4;     // f32 raw K [j=128][KSTR]
constexpr size_t FV  = FK  + 128 * KSTR * 4;     // f32 raw V x2 [128][VSTR]
constexpr size_t FP  = FV  + 2 * 128 * VSTR * 4; // u32 [m=128][ASTR] tf32 exp(P)
constexpr size_t FM  = FP  + 128 * ASTR * 4;
constexpr size_t FL  = FM  + 128 * 4;
constexpr size_t FMN = FL  + 128 * 4;
constexpr size_t FF  = FMN + 128 * 4;
constexpr size_t FR2 = FF  + 128 * 4;
constexpr size_t FTOT = FR2 + 128 * 4 * 4;       // ~209 KB
}

__device__ float g_q[(size_t)B * NH * S * HD];
__device__ float g_k[(size_t)B * NH * S * HD];
__device__ float g_v[(size_t)B * NH * S * HD];
__device__ float g_ctx[(size_t)B * S * H];
__device__ float g_m[(size_t)B * NH * S];
__device__ float g_linv[(size_t)B * NH * S];
__device__ float g_attn_fb[ATTN_ELEMS];

__device__ __forceinline__ uint32_t tf32_of(float x) {
    uint32_t y;
    asm("cvt.rna.tf32.f32 %0, %1;" : "=r"(y) : "f"(x));
    return y;
}
__device__ __forceinline__ void mma8(float c[4],
                                     uint32_t a0, uint32_t a1, uint32_t a2, uint32_t a3,
                                     uint32_t b0, uint32_t b1) {
    asm volatile(
        "mma.sync.aligned.m16n8k8.row.col.f32.tf32.tf32.f32 "
        "{%0,%1,%2,%3}, {%4,%5,%6,%7}, {%8,%9}, {%0,%1,%2,%3};"
        : "+f"(c[0]), "+f"(c[1]), "+f"(c[2]), "+f"(c[3])
        : "r"(a0), "r"(a1), "r"(a2), "r"(a3), "r"(b0), "r"(b1));
}
__device__ __forceinline__ void cp16(uint32_t s, const void* g) {
    asm volatile("cp.async.cg.shared.global [%0], [%1], 16;" :: "r"(s), "l"(g));
}
#define CP_COMMIT()  asm volatile("cp.async.commit_group;")
#define CP_WAIT(N)   asm volatile("cp.async.wait_group %0;" :: "n"(N))

// ---------------------------------------------------------------------------
// GEMM: C[M,N] = A[M,K] @ W[N,K]^T + bias[N]. cp.async double-buffered.
// Raw f32 smem [row][k] stride 20; tf32 cvt at fragment load.
// ---------------------------------------------------------------------------
template <int MODE>
__global__ __launch_bounds__(256, 2) void gemm_tf32(
    const float* __restrict__ A, const float* __restrict__ W,
    const float* __restrict__ bias, float* __restrict__ C,
    int M, int N, int K)
{
    __shared__ __align__(16) float As[2][128][20];
    __shared__ __align__(16) float Ws[2][128][20];

    const int tid  = threadIdx.x;
    const int lane = tid & 31, wid = tid >> 5;
    const int row0 = blockIdx.y * 128, col0 = blockIdx.x * 128;
    const int wm = (wid >> 2) * 64, wn = (wid & 3) * 32;
    const int g = lane >> 2, tig = lane & 3;

    // loader: thread covers row (tid>>1), 2 x 16B segs
    const int lrow = tid >> 1;
    const int lseg = (tid & 1) * 8;   // float offset: 0 or 8

    auto issue = [&](int buf, int k0) {
        const float* ga = A + (size_t)(row0 + lrow) * K + k0 + lseg;
        uint32_t sa = (uint32_t)__cvta_generic_to_shared(&As[buf][lrow][lseg]);
        cp16(sa, ga); cp16(sa + 16, ga + 4);
        const float* gw = W + (size_t)(col0 + lrow) * K + k0 + lseg;
        uint32_t sw = (uint32_t)__cvta_generic_to_shared(&Ws[buf][lrow][lseg]);
        cp16(sw, gw); cp16(sw + 16, gw + 4);
        CP_COMMIT();
    };

    float acc[4][4][4] = {};
    issue(0, 0);

    int cur = 0;
    for (int k0 = 0; k0 < K; k0 += 16) {
        if (k0 + 16 < K) { issue(cur ^ 1, k0 + 16); CP_WAIT(1); }
        else             { CP_WAIT(0); }
        __syncthreads();

#pragma unroll
        for (int kk = 0; kk < 16; kk += 8) {
            uint32_t a[4][4], b[4][2];
#pragma unroll
            for (int mt = 0; mt < 4; mt++) {
                int m = wm + mt * 16 + g;
                a[mt][0] = tf32_of(As[cur][m][kk + tig]);
                a[mt][1] = tf32_of(As[cur][m + 8][kk + tig]);
                a[mt][2] = tf32_of(As[cur][m][kk + tig + 4]);
                a[mt][3] = tf32_of(As[cur][m + 8][kk + tig + 4]);
            }
#pragma unroll
            for (int nt = 0; nt < 4; nt++) {
                int n = wn + nt * 8 + g;
                b[nt][0] = tf32_of(Ws[cur][n][kk + tig]);
                b[nt][1] = tf32_of(Ws[cur][n][kk + tig + 4]);
            }
#pragma unroll
            for (int mt = 0; mt < 4; mt++)
#pragma unroll
                for (int nt = 0; nt < 4; nt++)
                    mma8(acc[mt][nt], a[mt][0], a[mt][1], a[mt][2], a[mt][3],
                         b[nt][0], b[nt][1]);
        }
        __syncthreads();
        cur ^= 1;
    }

#pragma unroll
    for (int mt = 0; mt < 4; mt++) {
#pragma unroll
        for (int rr = 0; rr < 2; rr++) {
            int m = row0 + wm + mt * 16 + g + rr * 8;
#pragma unroll
            for (int nt = 0; nt < 4; nt++) {
                int n = col0 + wn + nt * 8 + 2 * tig;
                float v0 = acc[mt][nt][rr * 2 + 0] + bias[n];
                float v1 = acc[mt][nt][rr * 2 + 1] + bias[n + 1];
                if (MODE == 0) {
                    *reinterpret_cast<float2*>(C + (size_t)m * N + n) =
                        make_float2(v0, v1);
                } else {
                    int bb = m / S, ss = m % S;
                    int hh2 = n / HD, dd = n % HD;
                    *reinterpret_cast<float2*>(
                        C + (((size_t)bb * NH + hh2) * S + ss) * HD + dd) =
                        make_float2(v0, v1);
                }
            }
        }
    }
}

// ---------------------------------------------------------------------------
// Flash attention, cp.async-pipelined. V double-buffered (issued 1 tile
// ahead), K single-buffered (issued mid-iteration after score mma).
// ---------------------------------------------------------------------------
__global__ __launch_bounds__(256) void flash_attn(
    const float* __restrict__ Qp, const float* __restrict__ Kp,
    const float* __restrict__ Vp, float* __restrict__ attn,
    float* __restrict__ ctx, float* __restrict__ mout,
    float* __restrict__ linvout, const int* __restrict__ causal_p)
{
    extern __shared__ char smc[];
    uint32_t* Qs   = reinterpret_cast<uint32_t*>(smc + FQ);
    float*    Kraw = reinterpret_cast<float*>(smc + FK);
    float*    Vraw = reinterpret_cast<float*>(smc + FV);
    uint32_t* Ps   = reinterpret_cast<uint32_t*>(smc + FP);
    float* m_s  = reinterpret_cast<float*>(smc + FM);
    float* l_s  = reinterpret_cast<float*>(smc + FL);
    float* mn_s = reinterpret_cast<float*>(smc + FMN);
    float* f_s  = reinterpret_cast<float*>(smc + FF);
    float* r2   = reinterpret_cast<float*>(smc + FR2);

    const int row0 = ((int)gridDim.x - 1 - (int)blockIdx.x) * 128;
    const int z    = blockIdx.y;
    const int causal = *causal_p;

    const float* Qg = Qp + (size_t)z * S * HD;
    const float* Kg = Kp + (size_t)z * S * HD;
    const float* Vg = Vp + (size_t)z * S * HD;
    float* att = attn + (size_t)z * S * S;

    const int tid = threadIdx.x;
    const int lane = tid & 31, wid = tid >> 5;
    const int g = lane >> 2, tig = lane & 3;
    const int lr = tid >> 2, lk = (tid & 3) << 2;
    const float NEG = -CUDART_INF_F;

    const int wm  = (wid >> 2) * 64, wn  = (wid & 3) * 32;   // score warps 2x4
    const int wm2 = (wid >> 1) * 32, wn2 = (wid & 1) * 32;   // PV warps 4x2

    // loader indices (K/V tiles: 128 rows x 64 floats)
    const int trow = tid >> 1;
    const int tseg = (tid & 1) * 32;  // float offset 0 / 32 (8 x 16B chunks)

    auto issueK = [&](int j0) {
        const float* gk = Kg + (size_t)(j0 + trow) * HD + tseg;
        uint32_t sk = (uint32_t)__cvta_generic_to_shared(&Kraw[trow * KSTR + tseg]);
#pragma unroll
        for (int c = 0; c < 8; c++) cp16(sk + c * 16, gk + c * 4);
    };
    auto issueV = [&](int vb, int j0) {
        const float* gv = Vg + (size_t)(j0 + trow) * HD + tseg;
        uint32_t sv = (uint32_t)__cvta_generic_to_shared(
            &Vraw[(size_t)vb * 128 * VSTR + trow * VSTR + tseg]);
#pragma unroll
        for (int c = 0; c < 8; c++) cp16(sv + c * 16, gv + c * 4);
    };

    const int jend   = causal ? (row0 + 128) : S;
    const int ntiles = jend >> 7;

    // prologue: V(0) + K(0) as one group
    issueV(0, 0);
    issueK(0);
    CP_COMMIT();

    // load Q (128 x 64) -> tf32 [k][m]
#pragma unroll
    for (int k0 = 0; k0 < HD; k0 += 16) {
#pragma unroll
        for (int hh = 0; hh < 2; hh++) {
            int r = lr + hh * 64;
            float4 v = *reinterpret_cast<const float4*>(
                Qg + (size_t)(row0 + r) * HD + k0 + lk);
            Qs[(k0 + lk + 0) * ASTR + r] = tf32_of(v.x);
            Qs[(k0 + lk + 1) * ASTR + r] = tf32_of(v.y);
            Qs[(k0 + lk + 2) * ASTR + r] = tf32_of(v.z);
            Qs[(k0 + lk + 3) * ASTR + r] = tf32_of(v.w);
        }
    }
    if (tid < 128) { m_s[tid] = NEG; l_s[tid] = 0.f; }

    float acc2[2][4][4] = {};

    for (int ti = 0; ti < ntiles; ti++) {
        const int j0 = ti << 7;
        const int vb = ti & 1;
        const bool more = (ti + 1) < ntiles;

        if (more) { issueV(vb ^ 1, j0 + 128); CP_COMMIT(); CP_WAIT(1); }
        else      { CP_WAIT(0); }
        __syncthreads();   // K(ti), V(ti) visible; Q/stats ready on ti==0

        // --- scores: Q (tf32 smem) x K (raw smem, cvt on load) ---
        float acc[4][4][4] = {};
#pragma unroll
        for (int kk = 0; kk < HD; kk += 8) {
            uint32_t a[4][4], b[4][2];
#pragma unroll
            for (int mt = 0; mt < 4; mt++) {
                int m = wm + mt * 16 + g;
                a[mt][0] = Qs[(kk + tig) * ASTR + m];
                a[mt][1] = Qs[(kk + tig) * ASTR + m + 8];
                a[mt][2] = Qs[(kk + tig + 4) * ASTR + m];
                a[mt][3] = Qs[(kk + tig + 4) * ASTR + m + 8];
            }
#pragma unroll
            for (int nt = 0; nt < 4; nt++) {
                int n = wn + nt * 8 + g;
                b[nt][0] = tf32_of(Kraw[n * KSTR + kk + tig]);
                b[nt][1] = tf32_of(Kraw[n * KSTR + kk + tig + 4]);
            }
#pragma unroll
            for (int mt = 0; mt < 4; mt++)
#pragma unroll
                for (int nt = 0; nt < 4; nt++)
                    mma8(acc[mt][nt], a[mt][0], a[mt][1], a[mt][2], a[mt][3],
                         b[nt][0], b[nt][1]);
        }

        // --- scale + mask + raw attn write + row-max partials ---
#pragma unroll
        for (int mt = 0; mt < 4; mt++) {
#pragma unroll
            for (int rr = 0; rr < 2; rr++) {
                int lm = wm + mt * 16 + g + rr * 8;
                int m  = row0 + lm;
                float mx = NEG;
#pragma unroll
                for (int nt = 0; nt < 4; nt++) {
                    int n = j0 + wn + nt * 8 + 2 * tig;
                    float v0 = acc[mt][nt][rr * 2 + 0] * 0.125f;
                    float v1 = acc[mt][nt][rr * 2 + 1] * 0.125f;
                    if (causal) {
                        if (n > m)     v0 = NEG;
                        if (n + 1 > m) v1 = NEG;
                    }
                    acc[mt][nt][rr * 2 + 0] = v0;
                    acc[mt][nt][rr * 2 + 1] = v1;
                    mx = fmaxf(mx, fmaxf(v0, v1));
                    *reinterpret_cast<float2*>(att + (size_t)m * S + n) =
                        make_float2(v0, v1);
                }
                mx = fmaxf(mx, __shfl_xor_sync(0xffffffffu, mx, 1));
                mx = fmaxf(mx, __shfl_xor_sync(0xffffffffu, mx, 2));
                if (tig == 0) r2[lm * 4 + (wid & 3)] = mx;
            }
        }
        __syncthreads();   // B: score mma done, K consumed

        // prefetch next K while exp/PV run
        if (more) { issueK(j0 + 128); CP_COMMIT(); }

        if (tid < 128) {
            float mn = fmaxf(fmaxf(r2[tid * 4 + 0], r2[tid * 4 + 1]),
                             fmaxf(r2[tid * 4 + 2], r2[tid * 4 + 3]));
            mn = fmaxf(m_s[tid], mn);
            mn_s[tid] = mn;
            f_s[tid]  = __expf(m_s[tid] - mn);
        }
        __syncthreads();   // C

        // --- exp, stage tf32 P, row-sum partials ---
#pragma unroll
        for (int mt = 0; mt < 4; mt++) {
#pragma unroll
            for (int rr = 0; rr < 2; rr++) {
                int lm = wm + mt * 16 + g + rr * 8;
                float mn = mn_s[lm];
                float sme = 0.f;
#pragma unroll
                for (int nt = 0; nt < 4; nt++) {
                    int nl = wn + nt * 8 + 2 * tig;
                    float e0 = __expf(acc[mt][nt][rr * 2 + 0] - mn);
                    float e1 = __expf(acc[mt][nt][rr * 2 + 1] - mn);
                    sme += e0 + e1;
                    uint2 pe = make_uint2(tf32_of(e0), tf32_of(e1));
                    *reinterpret_cast<uint2*>(&Ps[lm * ASTR + nl]) = pe;
                }
                sme += __shfl_xor_sync(0xffffffffu, sme, 1);
                sme += __shfl_xor_sync(0xffffffffu, sme, 2);
                if (tig == 0) r2[lm * 4 + (wid & 3)] = sme;
            }
        }
        __syncthreads();   // D

        if (tid < 128) {
            float add = r2[tid * 4 + 0] + r2[tid * 4 + 1] +
                        r2[tid * 4 + 2] + r2[tid * 4 + 3];
            l_s[tid] = l_s[tid] * f_s[tid] + add;
            m_s[tid] = mn_s[tid];
        }

        // --- PV: rescale acc2, then P (tf32 smem) x V (raw smem, cvt) ---
#pragma unroll
        for (int mt = 0; mt < 2; mt++) {
#pragma unroll
            for (int rr = 0; rr < 2; rr++) {
                float f = f_s[wm2 + mt * 16 + g + rr * 8];
#pragma unroll
                for (int nt = 0; nt < 4; nt++) {
                    acc2[mt][nt][rr * 2 + 0] *= f;
                    acc2[mt][nt][rr * 2 + 1] *= f;
                }
            }
        }
        const float* Vb = Vraw + (size_t)vb * 128 * VSTR;
#pragma unroll
        for (int kk = 0; kk < 128; kk += 8) {
            uint32_t a[2][4], b[4][2];
#pragma unroll
            for (int mt = 0; mt < 2; mt++) {
                int m = wm2 + mt * 16 + g;
                a[mt][0] = Ps[m * ASTR + kk + tig];
                a[mt][1] = Ps[(m + 8) * ASTR + kk + tig];
                a[mt][2] = Ps[m * ASTR + kk + tig + 4];
                a[mt][3] = Ps[(m + 8) * ASTR + kk + tig + 4];
            }
#pragma unroll
            for (int nt = 0; nt < 4; nt++) {
                int n = wn2 + nt * 8 + g;
                b[nt][0] = tf32_of(Vb[(kk + tig) * VSTR + n]);
                b[nt][1] = tf32_of(Vb[(kk + tig + 4) * VSTR + n]);
            }
#pragma unroll
            for (int mt = 0; mt < 2; mt++)
#pragma unroll
                for (int nt = 0; nt < 4; nt++)
                    mma8(acc2[mt][nt], a[mt][0], a[mt][1], a[mt][2], a[mt][3],
                         b[nt][0], b[nt][1]);
        }
        __syncthreads();   // E: Ps/V consumed; stats updated
    }

    if (tid < 128) {
        float inv = 1.0f / l_s[tid];
        f_s[tid] = inv;
        mout[(size_t)z * S + row0 + tid]    = m_s[tid];
        linvout[(size_t)z * S + row0 + tid] = inv;
    }
    __syncthreads();

    const int bb = z / NH, hh2 = z % NH;
#pragma unroll
    for (int mt = 0; mt < 2; mt++) {
#pragma unroll
        for (int rr = 0; rr < 2; rr++) {
            int lm = wm2 + mt * 16 + g + rr * 8;
            float inv = f_s[lm];
            int m = row0 + lm;
#pragma unroll
            for (int nt = 0; nt < 4; nt++) {
                int n = wn2 + nt * 8 + 2 * tig;
                *reinterpret_cast<float2*>(
                    ctx + ((size_t)bb * S + m) * H + hh2 * HD + n) =
                    make_float2(acc2[mt][nt][rr * 2 + 0] * inv,
                                acc2[mt][nt][rr * 2 + 1] * inv);
            }
        }
    }
}

// ---------------------------------------------------------------------------
// Normalize attn: p = exp(raw - m) * linv for cols <= r; 0 above.
// ---------------------------------------------------------------------------
__global__ __launch_bounds__(256) void normalize_attn(
    float* __restrict__ attn, const float* __restrict__ mrow,
    const float* __restrict__ linv, const int* __restrict__ causal_p)
{
    const size_t row = blockIdx.x;
    const int causal = *causal_p;
    const int r = causal ? (int)(row % S) : (S - 1);
    const float m  = mrow[row];
    const float il = linv[row];
    float* p = attn + row * S;
    const int t = threadIdx.x;

#pragma unroll
    for (int it = 0; it < 2; it++) {
        int c = (t + 256 * it) << 2;
        float4 v = make_float4(0.f, 0.f, 0.f, 0.f);
        if (c <= r) {
            float4 raw = *reinterpret_cast<const float4*>(p + c);
            v.x = __expf(raw.x - m) * il;
            v.y = (c + 1 <= r) ? __expf(raw.y - m) * il : 0.f;
            v.z = (c + 2 <= r) ? __expf(raw.z - m) * il : 0.f;
            v.w = (c + 3 <= r) ? __expf(raw.w - m) * il : 0.f;
        }
        *reinterpret_cast<float4*>(p + c) = v;
    }
}

// ---------------------------------------------------------------------------
// Launch
// ---------------------------------------------------------------------------
extern "C" void kernel_launch(void* const* d_in, const int* in_sizes, int n_in,
                              void* d_out, int out_size)
{
    const float* query = (const float*)d_in[0];
    const float* key_  = (const float*)d_in[1];
    const float* value = (const float*)d_in[2];
    const float* Wq = (const float*)d_in[3];
    const float* bq = (const float*)d_in[4];
    const float* Wk = (const float*)d_in[5];
    const float* bk = (const float*)d_in[6];
    const float* Wv = (const float*)d_in[7];
    const float* bv = (const float*)d_in[8];
    const float* Wo = (const float*)d_in[9];
    const float* bo = (const float*)d_in[10];
    const int* causal = (const int*)d_in[11];

    float *qp, *kp, *vp, *cp, *mp, *lp, *afb;
    cudaGetSymbolAddress((void**)&qp, g_q);
    cudaGetSymbolAddress((void**)&kp, g_k);
    cudaGetSymbolAddress((void**)&vp, g_v);
    cudaGetSymbolAddress((void**)&cp, g_ctx);
    cudaGetSymbolAddress((void**)&mp, g_m);
    cudaGetSymbolAddress((void**)&lp, g_linv);
    cudaGetSymbolAddress((void**)&afb, g_attn_fb);

    float* out = (float*)d_out;
    float* attn = ((size_t)out_size >= OUT_ELEMS + ATTN_ELEMS) ? (out + OUT_ELEMS)
                                                               : afb;

    cudaFuncSetAttribute(flash_attn,
                         cudaFuncAttributeMaxDynamicSharedMemorySize,
                         (int)FTOT);

    dim3 gproj(H / 128, MROWS / 128);                 // (8, 64)
    gemm_tf32<1><<<gproj, 256>>>(query, Wq, bq, qp, MROWS, H, H);
    gemm_tf32<1><<<gproj, 256>>>(key_,  Wk, bk, kp, MROWS, H, H);
    gemm_tf32<1><<<gproj, 256>>>(value, Wv, bv, vp, MROWS, H, H);

    dim3 gfa(S / 128, B * NH);                        // (16, 64)
    flash_attn<<<gfa, 256, FTOT>>>(qp, kp, vp, attn, cp, mp, lp, causal);

    normalize_attn<<<B * NH * S, 256>>>(attn, mp, lp, causal);

    gemm_tf32<0><<<gproj, 256>>>(cp, Wo, bo, out, MROWS, H, H);
}

// round 11
// speedup vs baseline: 1.0037x; 1.0010x over previous
#include <cuda_runtime.h>
#include <math_constants.h>
#include <cstdint>

namespace {
constexpr int B  = 4;
constexpr int S  = 2048;
constexpr int H  = 1024;
constexpr int NH = 16;
constexpr int HD = 64;
constexpr int MROWS = B * S;  // 8192
constexpr size_t OUT_ELEMS  = (size_t)B * S * H;
constexpr size_t ATTN_ELEMS = (size_t)B * NH * S * S;

constexpr int ASTR = 132;   // tf32 staging stride (floats)
constexpr int KSTR = 68;    // raw K tile stride (floats)  (68%32==4 -> cf)
constexpr int VSTR = 72;    // raw V tile stride (floats)  (72%32==8 -> cf)

// flash smem layout (bytes)
constexpr size_t FQ  = 0;                        // u32 [64][ASTR] Q tf32 [k][m]
constexpr size_t FK  = FQ  + 64  * ASTR * 4;     // f32 raw K [j=128][KSTR]
constexpr size_t FV  = FK  + 128 * KSTR * 4;     // f32 raw V x2 [128][VSTR]
constexpr size_t FP  = FV  + 2 * 128 * VSTR * 4; // u32 [m=128][ASTR] tf32 exp(P)
constexpr size_t FM  = FP  + 128 * ASTR * 4;
constexpr size_t FL  = FM  + 128 * 4;
constexpr size_t FMN = FL  + 128 * 4;
constexpr size_t FF  = FMN + 128 * 4;
constexpr size_t FR2 = FF  + 128 * 4;
constexpr size_t FTOT = FR2 + 128 * 4 * 4;       // ~209 KB
}

__device__ float g_q[(size_t)B * NH * S * HD];
__device__ float g_k[(size_t)B * NH * S * HD];
__device__ float g_v[(size_t)B * NH * S * HD];
__device__ float g_ctx[(size_t)B * S * H];
__device__ float g_m[(size_t)B * NH * S];
__device__ float g_linv[(size_t)B * NH * S];
__device__ float g_attn_fb[ATTN_ELEMS];

__device__ __forceinline__ uint32_t tf32_of(float x) {
    uint32_t y;
    asm("cvt.rna.tf32.f32 %0, %1;" : "=r"(y) : "f"(x));
    return y;
}
__device__ __forceinline__ void mma8(float c[4],
                                     uint32_t a0, uint32_t a1, uint32_t a2, uint32_t a3,
                                     uint32_t b0, uint32_t b1) {
    asm volatile(
        "mma.sync.aligned.m16n8k8.row.col.f32.tf32.tf32.f32 "
        "{%0,%1,%2,%3}, {%4,%5,%6,%7}, {%8,%9}, {%0,%1,%2,%3};"
        : "+f"(c[0]), "+f"(c[1]), "+f"(c[2]), "+f"(c[3])
        : "r"(a0), "r"(a1), "r"(a2), "r"(a3), "r"(b0), "r"(b1));
}
__device__ __forceinline__ void cp16(uint32_t s, const void* g) {
    asm volatile("cp.async.cg.shared.global [%0], [%1], 16;" :: "r"(s), "l"(g));
}
#define CP_COMMIT()  asm volatile("cp.async.commit_group;")
#define CP_WAIT(N)   asm volatile("cp.async.wait_group %0;" :: "n"(N))

// ---------------------------------------------------------------------------
// GEMM: C[M,N] = A[M,K] @ W[N,K]^T + bias[N]. cp.async double-buffered.
// Raw f32 smem [row][k] stride 20; tf32 cvt at fragment load.
// ---------------------------------------------------------------------------
template <int MODE>
__global__ __launch_bounds__(256, 2) void gemm_tf32(
    const float* __restrict__ A, const float* __restrict__ W,
    const float* __restrict__ bias, float* __restrict__ C,
    int M, int N, int K)
{
    __shared__ __align__(16) float As[2][128][20];
    __shared__ __align__(16) float Ws[2][128][20];

    const int tid  = threadIdx.x;
    const int lane = tid & 31, wid = tid >> 5;
    const int row0 = blockIdx.y * 128, col0 = blockIdx.x * 128;
    const int wm = (wid >> 2) * 64, wn = (wid & 3) * 32;
    const int g = lane >> 2, tig = lane & 3;

    // loader: thread covers row (tid>>1), 2 x 16B segs
    const int lrow = tid >> 1;
    const int lseg = (tid & 1) * 8;   // float offset: 0 or 8

    auto issue = [&](int buf, int k0) {
        const float* ga = A + (size_t)(row0 + lrow) * K + k0 + lseg;
        uint32_t sa = (uint32_t)__cvta_generic_to_shared(&As[buf][lrow][lseg]);
        cp16(sa, ga); cp16(sa + 16, ga + 4);
        const float* gw = W + (size_t)(col0 + lrow) * K + k0 + lseg;
        uint32_t sw = (uint32_t)__cvta_generic_to_shared(&Ws[buf][lrow][lseg]);
        cp16(sw, gw); cp16(sw + 16, gw + 4);
        CP_COMMIT();
    };

    float acc[4][4][4] = {};
    issue(0, 0);

    int cur = 0;
    for (int k0 = 0; k0 < K; k0 += 16) {
        if (k0 + 16 < K) { issue(cur ^ 1, k0 + 16); CP_WAIT(1); }
        else             { CP_WAIT(0); }
        __syncthreads();

#pragma unroll
        for (int kk = 0; kk < 16; kk += 8) {
            uint32_t a[4][4], b[4][2];
#pragma unroll
            for (int mt = 0; mt < 4; mt++) {
                int m = wm + mt * 16 + g;
                a[mt][0] = tf32_of(As[cur][m][kk + tig]);
                a[mt][1] = tf32_of(As[cur][m + 8][kk + tig]);
                a[mt][2] = tf32_of(As[cur][m][kk + tig + 4]);
                a[mt][3] = tf32_of(As[cur][m + 8][kk + tig + 4]);
            }
#pragma unroll
            for (int nt = 0; nt < 4; nt++) {
                int n = wn + nt * 8 + g;
                b[nt][0] = tf32_of(Ws[cur][n][kk + tig]);
                b[nt][1] = tf32_of(Ws[cur][n][kk + tig + 4]);
            }
#pragma unroll
            for (int mt = 0; mt < 4; mt++)
#pragma unroll
                for (int nt = 0; nt < 4; nt++)
                    mma8(acc[mt][nt], a[mt][0], a[mt][1], a[mt][2], a[mt][3],
                         b[nt][0], b[nt][1]);
        }
        __syncthreads();
        cur ^= 1;
    }

#pragma unroll
    for (int mt = 0; mt < 4; mt++) {
#pragma unroll
        for (int rr = 0; rr < 2; rr++) {
            int m = row0 + wm + mt * 16 + g + rr * 8;
#pragma unroll
            for (int nt = 0; nt < 4; nt++) {
                int n = col0 + wn + nt * 8 + 2 * tig;
                float v0 = acc[mt][nt][rr * 2 + 0] + bias[n];
                float v1 = acc[mt][nt][rr * 2 + 1] + bias[n + 1];
                if (MODE == 0) {
                    *reinterpret_cast<float2*>(C + (size_t)m * N + n) =
                        make_float2(v0, v1);
                } else {
                    int bb = m / S, ss = m % S;
                    int hh2 = n / HD, dd = n % HD;
                    *reinterpret_cast<float2*>(
                        C + (((size_t)bb * NH + hh2) * S + ss) * HD + dd) =
                        make_float2(v0, v1);
                }
            }
        }
    }
}

// ---------------------------------------------------------------------------
// Flash attention, cp.async-pipelined. V double-buffered (issued 1 tile
// ahead), K single-buffered (issued mid-iteration after score mma).
// ---------------------------------------------------------------------------
__global__ __launch_bounds__(256) void flash_attn(
    const float* __restrict__ Qp, const float* __restrict__ Kp,
    const float* __restrict__ Vp, float* __restrict__ attn,
    float* __restrict__ ctx, float* __restrict__ mout,
    float* __restrict__ linvout, const int* __restrict__ causal_p)
{
    extern __shared__ char smc[];
    uint32_t* Qs   = reinterpret_cast<uint32_t*>(smc + FQ);
    float*    Kraw = reinterpret_cast<float*>(smc + FK);
    float*    Vraw = reinterpret_cast<float*>(smc + FV);
    uint32_t* Ps   = reinterpret_cast<uint32_t*>(smc + FP);
    float* m_s  = reinterpret_cast<float*>(smc + FM);
    float* l_s  = reinterpret_cast<float*>(smc + FL);
    float* mn_s = reinterpret_cast<float*>(smc + FMN);
    float* f_s  = reinterpret_cast<float*>(smc + FF);
    float* r2   = reinterpret_cast<float*>(smc + FR2);

    const int row0 = ((int)gridDim.x - 1 - (int)blockIdx.x) * 128;
    const int z    = blockIdx.y;
    const int causal = *causal_p;

    const float* Qg = Qp + (size_t)z * S * HD;
    const float* Kg = Kp + (size_t)z * S * HD;
    const float* Vg = Vp + (size_t)z * S * HD;
    float* att = attn + (size_t)z * S * S;

    const int tid = threadIdx.x;
    const int lane = tid & 31, wid = tid >> 5;
    const int g = lane >> 2, tig = lane & 3;
    const int lr = tid >> 2, lk = (tid & 3) << 2;
    const float NEG = -CUDART_INF_F;

    const int wm  = (wid >> 2) * 64, wn  = (wid & 3) * 32;   // score warps 2x4
    const int wm2 = (wid >> 1) * 32, wn2 = (wid & 1) * 32;   // PV warps 4x2

    // loader indices (K/V tiles: 128 rows x 64 floats)
    const int trow = tid >> 1;
    const int tseg = (tid & 1) * 32;  // float offset 0 / 32 (8 x 16B chunks)

    auto issueK = [&](int j0) {
        const float* gk = Kg + (size_t)(j0 + trow) * HD + tseg;
        uint32_t sk = (uint32_t)__cvta_generic_to_shared(&Kraw[trow * KSTR + tseg]);
#pragma unroll
        for (int c = 0; c < 8; c++) cp16(sk + c * 16, gk + c * 4);
    };
    auto issueV = [&](int vb, int j0) {
        const float* gv = Vg + (size_t)(j0 + trow) * HD + tseg;
        uint32_t sv = (uint32_t)__cvta_generic_to_shared(
            &Vraw[(size_t)vb * 128 * VSTR + trow * VSTR + tseg]);
#pragma unroll
        for (int c = 0; c < 8; c++) cp16(sv + c * 16, gv + c * 4);
    };

    const int jend   = causal ? (row0 + 128) : S;
    const int ntiles = jend >> 7;

    // prologue: V(0) + K(0) as one group
    issueV(0, 0);
    issueK(0);
    CP_COMMIT();

    // load Q (128 x 64) -> tf32 [k][m]
#pragma unroll
    for (int k0 = 0; k0 < HD; k0 += 16) {
#pragma unroll
        for (int hh = 0; hh < 2; hh++) {
            int r = lr + hh * 64;
            float4 v = *reinterpret_cast<const float4*>(
                Qg + (size_t)(row0 + r) * HD + k0 + lk);
            Qs[(k0 + lk + 0) * ASTR + r] = tf32_of(v.x);
            Qs[(k0 + lk + 1) * ASTR + r] = tf32_of(v.y);
            Qs[(k0 + lk + 2) * ASTR + r] = tf32_of(v.z);
            Qs[(k0 + lk + 3) * ASTR + r] = tf32_of(v.w);
        }
    }
    if (tid < 128) { m_s[tid] = NEG; l_s[tid] = 0.f; }

    float acc2[2][4][4] = {};

    for (int ti = 0; ti < ntiles; ti++) {
        const int j0 = ti << 7;
        const int vb = ti & 1;
        const bool more = (ti + 1) < ntiles;

        if (more) { issueV(vb ^ 1, j0 + 128); CP_COMMIT(); CP_WAIT(1); }
        else      { CP_WAIT(0); }
        __syncthreads();   // K(ti), V(ti) visible; Q/stats ready on ti==0

        // --- scores: Q (tf32 smem) x K (raw smem, cvt on load) ---
        float acc[4][4][4] = {};
#pragma unroll
        for (int kk = 0; kk < HD; kk += 8) {
            uint32_t a[4][4], b[4][2];
#pragma unroll
            for (int mt = 0; mt < 4; mt++) {
                int m = wm + mt * 16 + g;
                a[mt][0] = Qs[(kk + tig) * ASTR + m];
                a[mt][1] = Qs[(kk + tig) * ASTR + m + 8];
                a[mt][2] = Qs[(kk + tig + 4) * ASTR + m];
                a[mt][3] = Qs[(kk + tig + 4) * ASTR + m + 8];
            }
#pragma unroll
            for (int nt = 0; nt < 4; nt++) {
                int n = wn + nt * 8 + g;
                b[nt][0] = tf32_of(Kraw[n * KSTR + kk + tig]);
                b[nt][1] = tf32_of(Kraw[n * KSTR + kk + tig + 4]);
            }
#pragma unroll
            for (int mt = 0; mt < 4; mt++)
#pragma unroll
                for (int nt = 0; nt < 4; nt++)
                    mma8(acc[mt][nt], a[mt][0], a[mt][1], a[mt][2], a[mt][3],
                         b[nt][0], b[nt][1]);
        }

        // --- scale + mask + raw attn write + row-max partials ---
#pragma unroll
        for (int mt = 0; mt < 4; mt++) {
#pragma unroll
            for (int rr = 0; rr < 2; rr++) {
                int lm = wm + mt * 16 + g + rr * 8;
                int m  = row0 + lm;
                float mx = NEG;
#pragma unroll
                for (int nt = 0; nt < 4; nt++) {
                    int n = j0 + wn + nt * 8 + 2 * tig;
                    float v0 = acc[mt][nt][rr * 2 + 0] * 0.125f;
                    float v1 = acc[mt][nt][rr * 2 + 1] * 0.125f;
                    if (causal) {
                        if (n > m)     v0 = NEG;
                        if (n + 1 > m) v1 = NEG;
                    }
                    acc[mt][nt][rr * 2 + 0] = v0;
                    acc[mt][nt][rr * 2 + 1] = v1;
                    mx = fmaxf(mx, fmaxf(v0, v1));
                    *reinterpret_cast<float2*>(att + (size_t)m * S + n) =
                        make_float2(v0, v1);
                }
                mx = fmaxf(mx, __shfl_xor_sync(0xffffffffu, mx, 1));
                mx = fmaxf(mx, __shfl_xor_sync(0xffffffffu, mx, 2));
                if (tig == 0) r2[lm * 4 + (wid & 3)] = mx;
            }
        }
        __syncthreads();   // B: score mma done, K consumed

        // prefetch next K while exp/PV run
        if (more) { issueK(j0 + 128); CP_COMMIT(); }

        if (tid < 128) {
            float mn = fmaxf(fmaxf(r2[tid * 4 + 0], r2[tid * 4 + 1]),
                             fmaxf(r2[tid * 4 + 2], r2[tid * 4 + 3]));
            mn = fmaxf(m_s[tid], mn);
            mn_s[tid] = mn;
            f_s[tid]  = __expf(m_s[tid] - mn);
        }
        __syncthreads();   // C

        // --- exp, stage tf32 P, row-sum partials ---
#pragma unroll
        for (int mt = 0; mt < 4; mt++) {
#pragma unroll
            for (int rr = 0; rr < 2; rr++) {
                int lm = wm + mt * 16 + g + rr * 8;
                float mn = mn_s[lm];
                float sme = 0.f;
#pragma unroll
                for (int nt = 0; nt < 4; nt++) {
                    int nl = wn + nt * 8 + 2 * tig;
                    float e0 = __expf(acc[mt][nt][rr * 2 + 0] - mn);
                    float e1 = __expf(acc[mt][nt][rr * 2 + 1] - mn);
                    sme += e0 + e1;
                    uint2 pe = make_uint2(tf32_of(e0), tf32_of(e1));
                    *reinterpret_cast<uint2*>(&Ps[lm * ASTR + nl]) = pe;
                }
                sme += __shfl_xor_sync(0xffffffffu, sme, 1);
                sme += __shfl_xor_sync(0xffffffffu, sme, 2);
                if (tig == 0) r2[lm * 4 + (wid & 3)] = sme;
            }
        }
        __syncthreads();   // D

        if (tid < 128) {
            float add = r2[tid * 4 + 0] + r2[tid * 4 + 1] +
                        r2[tid * 4 + 2] + r2[tid * 4 + 3];
            l_s[tid] = l_s[tid] * f_s[tid] + add;
            m_s[tid] = mn_s[tid];
        }

        // --- PV: rescale acc2, then P (tf32 smem) x V (raw smem, cvt) ---
#pragma unroll
        for (int mt = 0; mt < 2; mt++) {
#pragma unroll
            for (int rr = 0; rr < 2; rr++) {
                float f = f_s[wm2 + mt * 16 + g + rr * 8];
#pragma unroll
                for (int nt = 0; nt < 4; nt++) {
                    acc2[mt][nt][rr * 2 + 0] *= f;
                    acc2[mt][nt][rr * 2 + 1] *= f;
                }
            }
        }
        const float* Vb = Vraw + (size_t)vb * 128 * VSTR;
#pragma unroll
        for (int kk = 0; kk < 128; kk += 8) {
            uint32_t a[2][4], b[4][2];
#pragma unroll
            for (int mt = 0; mt < 2; mt++) {
                int m = wm2 + mt * 16 + g;
                a[mt][0] = Ps[m * ASTR + kk + tig];
                a[mt][1] = Ps[(m + 8) * ASTR + kk + tig];
                a[mt][2] = Ps[m * ASTR + kk + tig + 4];
                a[mt][3] = Ps[(m + 8) * ASTR + kk + tig + 4];
            }
#pragma unroll
            for (int nt = 0; nt < 4; nt++) {
                int n = wn2 + nt * 8 + g;
                b[nt][0] = tf32_of(Vb[(kk + tig) * VSTR + n]);
                b[nt][1] = tf32_of(Vb[(kk + tig + 4) * VSTR + n]);
            }
#pragma unroll
            for (int mt = 0; mt < 2; mt++)
#pragma unroll
                for (int nt = 0; nt < 4; nt++)
                    mma8(acc2[mt][nt], a[mt][0], a[mt][1], a[mt][2], a[mt][3],
                         b[nt][0], b[nt][1]);
        }
        __syncthreads();   // E: Ps/V consumed; stats updated
    }

    if (tid < 128) {
        float inv = 1.0f / l_s[tid];
        f_s[tid] = inv;
        mout[(size_t)z * S + row0 + tid]    = m_s[tid];
        linvout[(size_t)z * S + row0 + tid] = inv;
    }
    __syncthreads();

    const int bb = z / NH, hh2 = z % NH;
#pragma unroll
    for (int mt = 0; mt < 2; mt++) {
#pragma unroll
        for (int rr = 0; rr < 2; rr++) {
            int lm = wm2 + mt * 16 + g + rr * 8;
            float inv = f_s[lm];
            int m = row0 + lm;
#pragma unroll
            for (int nt = 0; nt < 4; nt++) {
                int n = wn2 + nt * 8 + 2 * tig;
                *reinterpret_cast<float2*>(
                    ctx + ((size_t)bb * S + m) * H + hh2 * HD + n) =
                    make_float2(acc2[mt][nt][rr * 2 + 0] * inv,
                                acc2[mt][nt][rr * 2 + 1] * inv);
            }
        }
    }
}

// ---------------------------------------------------------------------------
// Normalize attn: p = exp(raw - m) * linv for cols <= r; 0 above.
// ---------------------------------------------------------------------------
__global__ __launch_bounds__(256) void normalize_attn(
    float* __restrict__ attn, const float* __restrict__ mrow,
    const float* __restrict__ linv, const int* __restrict__ causal_p)
{
    const size_t row = blockIdx.x;
    const int causal = *causal_p;
    const int r = causal ? (int)(row % S) : (S - 1);
    const float m  = mrow[row];
    const float il = linv[row];
    float* p = attn + row * S;
    const int t = threadIdx.x;

#pragma unroll
    for (int it = 0; it < 2; it++) {
        int c = (t + 256 * it) << 2;
        float4 v = make_float4(0.f, 0.f, 0.f, 0.f);
        if (c <= r) {
            float4 raw = *reinterpret_cast<const float4*>(p + c);
            v.x = __expf(raw.x - m) * il;
            v.y = (c + 1 <= r) ? __expf(raw.y - m) * il : 0.f;
            v.z = (c + 2 <= r) ? __expf(raw.z - m) * il : 0.f;
            v.w = (c + 3 <= r) ? __expf(raw.w - m) * il : 0.f;
        }
        *reinterpret_cast<float4*>(p + c) = v;
    }
}

// ---------------------------------------------------------------------------
// Launch
// ---------------------------------------------------------------------------
extern "C" void kernel_launch(void* const* d_in, const int* in_sizes, int n_in,
                              void* d_out, int out_size)
{
    const float* query = (const float*)d_in[0];
    const float* key_  = (const float*)d_in[1];
    const float* value = (const float*)d_in[2];
    const float* Wq = (const float*)d_in[3];
    const float* bq = (const float*)d_in[4];
    const float* Wk = (const float*)d_in[5];
    const float* bk = (const float*)d_in[6];
    const float* Wv = (const float*)d_in[7];
    const float* bv = (const float*)d_in[8];
    const float* Wo = (const float*)d_in[9];
    const float* bo = (const float*)d_in[10];
    const int* causal = (const int*)d_in[11];

    float *qp, *kp, *vp, *cp, *mp, *lp, *afb;
    cudaGetSymbolAddress((void**)&qp, g_q);
    cudaGetSymbolAddress((void**)&kp, g_k);
    cudaGetSymbolAddress((void**)&vp, g_v);
    cudaGetSymbolAddress((void**)&cp, g_ctx);
    cudaGetSymbolAddress((void**)&mp, g_m);
    cudaGetSymbolAddress((void**)&lp, g_linv);
    cudaGetSymbolAddress((void**)&afb, g_attn_fb);

    float* out = (float*)d_out;
    float* attn = ((size_t)out_size >= OUT_ELEMS + ATTN_ELEMS) ? (out + OUT_ELEMS)
                                                               : afb;

    cudaFuncSetAttribute(flash_attn,
                         cudaFuncAttributeMaxDynamicSharedMemorySize,
                         (int)FTOT);

    dim3 gproj(H / 128, MROWS / 128);                 // (8, 64)
    gemm_tf32<1><<<gproj, 256>>>(query, Wq, bq, qp, MROWS, H, H);
    gemm_tf32<1><<<gproj, 256>>>(key_,  Wk, bk, kp, MROWS, H, H);
    gemm_tf32<1><<<gproj, 256>>>(value, Wv, bv, vp, MROWS, H, H);

    dim3 gfa(S / 128, B * NH);                        // (16, 64)
    flash_attn<<<gfa, 256, FTOT>>>(qp, kp, vp, attn, cp, mp, lp, causal);

    normalize_attn<<<B * NH * S, 256>>>(attn, mp, lp, causal);

    gemm_tf32<0><<<gproj, 256>>>(cp, Wo, bo, out, MROWS, H, H);
}